// round 3
// baseline (speedup 1.0000x reference)
#include <cuda_runtime.h>

// CARAFE3D: x[2,32,32,32,32] -> out[2,16,64,64,64]
// Pipeline:
//   K0: transpose w_enc -> WT[kk][oc], build im2col tap tables
//   K1: t = W_down@x + b_down (8ch), z = W_out@x (16ch, bias deferred)
//   K2: enc GEMM: enc[gv][216] = W_enc @ im2col(t) + b_enc
//       (224oc x 128v block tile, 448 thr, double-buffered, f32x2)
//   K3: softmax over k per r + reassembly with z + pixel-shuffle + b_out
//       (2 threads per voxel, 8 channels each)
typedef unsigned long long ull;

#define VOX 32768
#define GV_TOTAL 65536

__device__ float g_t[2 * 8 * VOX];
__device__ float g_z[2 * 16 * VOX];
__device__ float g_wt[216 * 216];
__device__ float g_enc[(size_t)GV_TOTAL * 216];
__device__ int g_tapdelta[216];
__device__ int g_tap_h[216];
__device__ int g_tap_w[216];
__device__ int g_tap_d[216];

__device__ __forceinline__ ull dup2(float a) {
    ull r; unsigned u = __float_as_uint(a);
    asm("mov.b64 %0, {%1, %1};" : "=l"(r) : "r"(u));
    return r;
}
__device__ __forceinline__ ull pack2(float a, float b) {
    ull r;
    asm("mov.b64 %0, {%1, %2};" : "=l"(r)
        : "r"(__float_as_uint(a)), "r"(__float_as_uint(b)));
    return r;
}
__device__ __forceinline__ void unpack2(ull v, float& x, float& y) {
    unsigned a, b;
    asm("mov.b64 {%0, %1}, %2;" : "=r"(a), "=r"(b) : "l"(v));
    x = __uint_as_float(a); y = __uint_as_float(b);
}
__device__ __forceinline__ ull ffma2(ull a, ull b, ull c) {
    ull d;
    asm("fma.rn.f32x2 %0, %1, %2, %3;" : "=l"(d) : "l"(a), "l"(b), "l"(c));
    return d;
}

// ---------------- K0: weight transpose + tap tables ----------------
__global__ void k_transpose(const float* __restrict__ w_enc) {
    int i = blockIdx.x * 256 + threadIdx.x;
    if (i < 216 * 216) {
        int kk = i / 216;
        int oc = i - kk * 216;
        g_wt[i] = w_enc[oc * 216 + kk];
    }
    if (i < 216) {
        int ci = i / 27;
        int tap = i - ci * 27;
        int th = tap / 9;
        int tr = tap - th * 9;
        int tw = tr / 3;
        int td = tr - tw * 3;
        g_tapdelta[i] = ci * VOX + (th - 1) * 1024 + (tw - 1) * 32 + (td - 1);
        g_tap_h[i] = th - 1;
        g_tap_w[i] = tw - 1;
        g_tap_d[i] = td - 1;
    }
}

// ---------------- K1: down-projection t and output-projection z ----------------
__global__ __launch_bounds__(256) void k_down(
    const float* __restrict__ x,
    const float* __restrict__ wd, const float* __restrict__ bd,
    const float* __restrict__ wo)
{
    __shared__ float swd[8 * 32];
    __shared__ float swo[16 * 32];
    int tid = threadIdx.x;
    if (tid < 256) swd[tid] = wd[tid];
    swo[tid] = wo[tid];
    swo[tid + 256] = wo[tid + 256];
    __syncthreads();

    int gv = blockIdx.x * 256 + tid;
    int n = gv >> 15;
    int loc = gv & (VOX - 1);
    const float* xb = x + n * (32 * VOX) + loc;

    float xv[32];
#pragma unroll
    for (int c = 0; c < 32; c++) xv[c] = xb[c * VOX];

#pragma unroll
    for (int m = 0; m < 8; m++) {
        float acc = bd[m];
#pragma unroll
        for (int c = 0; c < 32; c++) acc += swd[m * 32 + c] * xv[c];
        g_t[(n * 8 + m) * VOX + loc] = acc;
    }
#pragma unroll
    for (int m = 0; m < 16; m++) {
        float acc = 0.f;
#pragma unroll
        for (int c = 0; c < 32; c++) acc += swo[m * 32 + c] * xv[c];
        g_z[(n * 16 + m) * VOX + loc] = acc;
    }
}

// ---------------- K2: encoder GEMM ----------------
// Block tile: 224 oc (216 + 8 zero-pad) x 128 voxels, K=216 in 27 chunks of 8.
// 448 threads = 28 ty (8 oc rows each) x 16 tx (8 voxels each, f32x2 pairs).
// Double-buffered A/B smem staging: one barrier per chunk.
struct TapS { int delta, dh, dw, dd; };

__device__ __forceinline__ void stage_chunk(
    float* As, float* Bs, const TapS* taps,
    int tid, int chunk, int loc0, int base_t)
{
    // A: 8 x 224 floats (zero-padded oc 216..223), coalesced from g_wt
#pragma unroll
    for (int i = 0; i < 4; i++) {
        int idx = tid + i * 448;
        int kkL = idx / 224;
        int oc = idx - kkL * 224;
        float v = 0.f;
        if (oc < 216) v = g_wt[(chunk * 8 + kkL) * 216 + oc];
        As[kkL * 224 + oc] = v;
    }
    // B: 8 x 128 im2col of t with border predication via tap tables
#pragma unroll
    for (int i = 0; i < 3; i++) {
        int idx = tid + i * 448;
        if (idx < 1024) {
            int kkL = idx >> 7;
            int v = idx & 127;
            TapS tp = taps[chunk * 8 + kkL];
            int loc = loc0 + v;
            int h = loc >> 10, w = (loc >> 5) & 31, d = loc & 31;
            float val = 0.f;
            if ((unsigned)(h + tp.dh) < 32u && (unsigned)(w + tp.dw) < 32u &&
                (unsigned)(d + tp.dd) < 32u)
                val = g_t[base_t + loc + tp.delta];
            Bs[kkL * 128 + v] = val;
        }
    }
}

__global__ __launch_bounds__(448) void k_enc(const float* __restrict__ b_enc) {
    __shared__ __align__(16) float A_s[2][8 * 224];
    __shared__ __align__(16) float B_s[2][8 * 128];
    __shared__ TapS s_tap[216];

    int tid = threadIdx.x;
    if (tid < 216) {
        TapS tp;
        tp.delta = g_tapdelta[tid];
        tp.dh = g_tap_h[tid];
        tp.dw = g_tap_w[tid];
        tp.dd = g_tap_d[tid];
        s_tap[tid] = tp;
    }
    int ty = tid >> 4;        // 0..27 (ty==27 -> padded oc)
    int tx = tid & 15;        // 0..15 -> voxels tx*8..tx*8+7
    int gv0 = blockIdx.x * 128;
    int nb = gv0 >> 15;
    int loc0 = gv0 & (VOX - 1);
    int base_t = nb * 8 * VOX;

    __syncthreads();          // taps visible
    stage_chunk(A_s[0], B_s[0], s_tap, tid, 0, loc0, base_t);
    __syncthreads();

    ull acc[8][4];
#pragma unroll
    for (int m = 0; m < 8; m++)
#pragma unroll
        for (int p = 0; p < 4; p++) acc[m][p] = 0ull;

    int buf = 0;
    for (int chunk = 0; chunk < 27; chunk++) {
        if (chunk < 26)
            stage_chunk(A_s[buf ^ 1], B_s[buf ^ 1], s_tap, tid, chunk + 1, loc0, base_t);

#pragma unroll
        for (int kk = 0; kk < 8; kk++) {
            const float4 a0 = *(const float4*)(A_s[buf] + kk * 224 + ty * 8);
            const float4 a1 = *(const float4*)(A_s[buf] + kk * 224 + ty * 8 + 4);
            ull av[8];
            av[0] = dup2(a0.x); av[1] = dup2(a0.y); av[2] = dup2(a0.z); av[3] = dup2(a0.w);
            av[4] = dup2(a1.x); av[5] = dup2(a1.y); av[6] = dup2(a1.z); av[7] = dup2(a1.w);
            const ulonglong2 b0 = *(const ulonglong2*)(B_s[buf] + kk * 128 + tx * 8);
            const ulonglong2 b1 = *(const ulonglong2*)(B_s[buf] + kk * 128 + tx * 8 + 4);
            ull bv[4] = { b0.x, b0.y, b1.x, b1.y };
#pragma unroll
            for (int m = 0; m < 8; m++)
#pragma unroll
                for (int p = 0; p < 4; p++)
                    acc[m][p] = ffma2(av[m], bv[p], acc[m][p]);
        }
        __syncthreads();
        buf ^= 1;
    }

    if (ty >= 27) return;     // padded oc rows

    float bb[8];
#pragma unroll
    for (int m = 0; m < 8; m++) bb[m] = b_enc[ty * 8 + m];

#pragma unroll
    for (int p = 0; p < 4; p++) {
        float lo[8], hi[8];
#pragma unroll
        for (int m = 0; m < 8; m++) unpack2(acc[m][p], lo[m], hi[m]);
        int v0 = tx * 8 + 2 * p;          // voxel pair (v0, v0+1)

        float4 q0, q1;
        q0.x = lo[0] + bb[0]; q0.y = lo[1] + bb[1]; q0.z = lo[2] + bb[2]; q0.w = lo[3] + bb[3];
        q1.x = lo[4] + bb[4]; q1.y = lo[5] + bb[5]; q1.z = lo[6] + bb[6]; q1.w = lo[7] + bb[7];
        size_t off0 = (size_t)(gv0 + v0) * 216 + ty * 8;
        *(float4*)(g_enc + off0) = q0;
        *(float4*)(g_enc + off0 + 4) = q1;

        q0.x = hi[0] + bb[0]; q0.y = hi[1] + bb[1]; q0.z = hi[2] + bb[2]; q0.w = hi[3] + bb[3];
        q1.x = hi[4] + bb[4]; q1.y = hi[5] + bb[5]; q1.z = hi[6] + bb[6]; q1.w = hi[7] + bb[7];
        size_t off1 = off0 + 216;
        *(float4*)(g_enc + off1) = q0;
        *(float4*)(g_enc + off1 + 4) = q1;
    }
}

// ---------------- K3: softmax + reassembly + pixel shuffle + bias ----------------
// 2 threads per voxel, 8 output channels each: acc[8][4] (rd packed in f32x2),
// q = rh*2+rw. Warp lanes are voxel-fast -> coalesced z / enc / out accesses.
__global__ __launch_bounds__(256) void k_out(const float* __restrict__ b_out,
                                             float* __restrict__ out)
{
    int tid = threadIdx.x;
    int vloc = tid & 127;
    int cg = tid >> 7;                    // 0 -> c 0..7, 1 -> c 8..15
    int gv = blockIdx.x * 128 + vloc;
    int n = gv >> 15;
    int loc = gv & (VOX - 1);
    int h = loc >> 10, w = (loc >> 5) & 31, d = loc & 31;

    const float* erow = g_enc + (size_t)gv * 216;
    const float* zb = g_z + (n * 16 + cg * 8) * VOX;

    ull acc[8][4];
#pragma unroll
    for (int c = 0; c < 8; c++)
#pragma unroll
        for (int q = 0; q < 4; q++) acc[c][q] = 0ull;
    float Z[8];
#pragma unroll
    for (int r = 0; r < 8; r++) Z[r] = 0.f;

#pragma unroll
    for (int k = 0; k < 27; k++) {
        const int th = k / 9 - 1;
        const int tw = (k / 3) % 3 - 1;
        const int td = k % 3 - 1;
        int hh = h + th, ww = w + tw, dd = d + td;
        bool ok = ((unsigned)hh < 32u) && ((unsigned)ww < 32u) && ((unsigned)dd < 32u);
        int zoff = (hh << 10) + (ww << 5) + dd;

        float4 e0 = *(const float4*)(erow + k * 8);
        float4 e1 = *(const float4*)(erow + k * 8 + 4);
        // enc values bounded (~|6|) for this net: exp without max-shift is safe.
        float p0 = __expf(e0.x), p1 = __expf(e0.y), p2 = __expf(e0.z), p3 = __expf(e0.w);
        float p4 = __expf(e1.x), p5 = __expf(e1.y), p6 = __expf(e1.z), p7 = __expf(e1.w);
        Z[0] += p0; Z[1] += p1; Z[2] += p2; Z[3] += p3;
        Z[4] += p4; Z[5] += p5; Z[6] += p6; Z[7] += p7;
        ull kr0 = pack2(p0, p1), kr1 = pack2(p2, p3);
        ull kr2 = pack2(p4, p5), kr3 = pack2(p6, p7);

#pragma unroll
        for (int c = 0; c < 8; c++) {
            float zv = ok ? __ldg(zb + c * VOX + zoff) : 0.f;
            ull z2 = dup2(zv);
            acc[c][0] = ffma2(kr0, z2, acc[c][0]);
            acc[c][1] = ffma2(kr1, z2, acc[c][1]);
            acc[c][2] = ffma2(kr2, z2, acc[c][2]);
            acc[c][3] = ffma2(kr3, z2, acc[c][3]);
        }
    }

    ull iz[4];
    {
        float i0 = 1.f / Z[0], i1 = 1.f / Z[1], i2 = 1.f / Z[2], i3 = 1.f / Z[3];
        float i4 = 1.f / Z[4], i5 = 1.f / Z[5], i6 = 1.f / Z[6], i7 = 1.f / Z[7];
        iz[0] = pack2(i0, i1); iz[1] = pack2(i2, i3);
        iz[2] = pack2(i4, i5); iz[3] = pack2(i6, i7);
    }

#pragma unroll
    for (int cc = 0; cc < 8; cc++) {
        int c = cg * 8 + cc;
        ull b2 = dup2(b_out[c]);
        int cbase = (n * 16 + c) * 64;
#pragma unroll
        for (int q = 0; q < 4; q++) {
            int rh = q >> 1, rw = q & 1;
            ull res = ffma2(acc[cc][q], iz[q], b2);   // acc/Z + b_out, both rd lanes
            int addr = (((cbase + h * 2 + rh) * 64) + (w * 2 + rw)) * 64 + d * 2;
            *(ull*)(out + addr) = res;                // coalesced float2 store
        }
    }
}

extern "C" void kernel_launch(void* const* d_in, const int* in_sizes, int n_in,
                              void* d_out, int out_size) {
    const float* x      = (const float*)d_in[0];
    const float* w_down = (const float*)d_in[1];
    const float* b_down = (const float*)d_in[2];
    const float* w_enc  = (const float*)d_in[3];
    const float* b_enc  = (const float*)d_in[4];
    const float* w_out  = (const float*)d_in[5];
    const float* b_out  = (const float*)d_in[6];
    float* out = (float*)d_out;

    k_transpose<<<(216 * 216 + 255) / 256, 256>>>(w_enc);
    k_down<<<GV_TOTAL / 256, 256>>>(x, w_down, b_down, w_out);
    k_enc<<<GV_TOTAL / 128, 448>>>(b_enc);
    k_out<<<GV_TOTAL / 128, 256>>>(b_out, out);
}

// round 6
// speedup vs baseline: 1.7062x; 1.7062x over previous
#include <cuda_runtime.h>
#include <cuda_bf16.h>
#include <cstdint>

// CARAFE3D: x[2,32,32,32,32] -> out[2,16,64,64,64]
//   k_prep: W_enc -> bf16 hi/lo split, chunked [k16step][split][oc224][k16]; tap tables
//   k_down: t = W_down@x + b_down (8ch), z = W_out@x (16ch)
//   k_enc : enc[gv][216] = W_enc @ im2col(t) + b_enc  via mma.sync bf16 3-pass split
//   k_out : softmax over k per r + reassembly with z + pixel shuffle + b_out
typedef unsigned long long ull;
typedef unsigned int u32;

#define VOX 32768
#define GV_TOTAL 65536

__device__ float g_t[2 * 8 * VOX];
__device__ float g_z[2 * 16 * VOX];
__device__ __align__(16) unsigned short g_wp[14 * 2 * 224 * 16];  // bf16 bits
__device__ float g_enc[(size_t)GV_TOTAL * 216];
__device__ int g_tapdelta[224];
__device__ int g_tap_h[224];
__device__ int g_tap_w[224];
__device__ int g_tap_d[224];

__device__ __forceinline__ ull dup2(float a) {
    ull r; unsigned u = __float_as_uint(a);
    asm("mov.b64 %0, {%1, %1};" : "=l"(r) : "r"(u));
    return r;
}
__device__ __forceinline__ ull pack2(float a, float b) {
    ull r;
    asm("mov.b64 %0, {%1, %2};" : "=l"(r) : "r"(__float_as_uint(a)), "r"(__float_as_uint(b)));
    return r;
}
__device__ __forceinline__ ull ffma2(ull a, ull b, ull c) {
    ull d;
    asm("fma.rn.f32x2 %0, %1, %2, %3;" : "=l"(d) : "l"(a), "l"(b), "l"(c));
    return d;
}
#define MMA_BF16(d, a, b0_, b1_) \
    asm volatile("mma.sync.aligned.m16n8k16.row.col.f32.bf16.bf16.f32 " \
        "{%0,%1,%2,%3}, {%4,%5,%6,%7}, {%8,%9}, {%0,%1,%2,%3};" \
        : "+f"((d)[0]), "+f"((d)[1]), "+f"((d)[2]), "+f"((d)[3]) \
        : "r"((a)[0]), "r"((a)[1]), "r"((a)[2]), "r"((a)[3]), "r"(b0_), "r"(b1_))

// ---------------- k_prep: weight split + chunk layout + tap tables ----------------
// Global W layout: [kstep 14][split 2][oc 224][k 16] bf16 (zeros in padding).
__global__ void k_prep(const float* __restrict__ w_enc) {
    int i = blockIdx.x * 256 + threadIdx.x;
    if (i < 224 * 224) {
        int oc = i / 224;
        int k = i - oc * 224;
        float v = (oc < 216 && k < 216) ? w_enc[oc * 216 + k] : 0.f;
        __nv_bfloat16 hb = __float2bfloat16(v);
        float hf = __bfloat162float(hb);
        __nv_bfloat16 lb = __float2bfloat16(v - hf);
        int off = (((k >> 4) * 2) * 224 + oc) * 16 + (k & 15);
        g_wp[off] = *(unsigned short*)&hb;
        g_wp[off + 224 * 16] = *(unsigned short*)&lb;
    }
    if (i < 224) {
        if (i < 216) {
            int ci = i / 27;
            int tap = i - ci * 27;
            int th = tap / 9;
            int tr = tap - th * 9;
            int tw = tr / 3;
            int td = tr - tw * 3;
            g_tapdelta[i] = ci * VOX + (th - 1) * 1024 + (tw - 1) * 32 + (td - 1);
            g_tap_h[i] = th - 1; g_tap_w[i] = tw - 1; g_tap_d[i] = td - 1;
        } else {
            g_tapdelta[i] = 0; g_tap_h[i] = 99; g_tap_w[i] = 99; g_tap_d[i] = 99;
        }
    }
}

// ---------------- k_down ----------------
__global__ __launch_bounds__(256) void k_down(
    const float* __restrict__ x,
    const float* __restrict__ wd, const float* __restrict__ bd,
    const float* __restrict__ wo)
{
    __shared__ float swd[8 * 32];
    __shared__ float swo[16 * 32];
    int tid = threadIdx.x;
    if (tid < 256) swd[tid] = wd[tid];
    swo[tid] = wo[tid];
    swo[tid + 256] = wo[tid + 256];
    __syncthreads();

    int gv = blockIdx.x * 256 + tid;
    int n = gv >> 15;
    int loc = gv & (VOX - 1);
    const float* xb = x + n * (32 * VOX) + loc;

    float xv[32];
#pragma unroll
    for (int c = 0; c < 32; c++) xv[c] = xb[c * VOX];
#pragma unroll
    for (int m = 0; m < 8; m++) {
        float acc = bd[m];
#pragma unroll
        for (int c = 0; c < 32; c++) acc += swd[m * 32 + c] * xv[c];
        g_t[(n * 8 + m) * VOX + loc] = acc;
    }
#pragma unroll
    for (int m = 0; m < 16; m++) {
        float acc = 0.f;
#pragma unroll
        for (int c = 0; c < 32; c++) acc += swo[m * 32 + c] * xv[c];
        g_z[(n * 16 + m) * VOX + loc] = acc;
    }
}

// ---------------- k_enc: bf16 mma.sync GEMM with 3-pass split ----------------
// Block: 64 voxels x 224 oc; 8 warps = 2(M) x 4(N); warp tile 32 x 56.
// K = 224 (216 + zero pad), 14 chunks of 16, double buffered.
// Smem rows padded to 40 bf16 (20 words) -> conflict-free fragment LDS.
struct TapS { int delta, dh, dw, dd; };

#define TAP_OFF 0
#define A_OFF 3584
#define A_SZ 5120           // 64 x 40 bf16
#define B_OFF 24064
#define B_SZ 17920          // 224 x 40 bf16
#define SMEM_ENC 95744

__device__ __forceinline__ void stage_chunk(
    char* smem, int buf, int chunk, int tid, int loc0, int base_t)
{
    // B: [split][oc 224][k16] from global, 896 uint4, into stride-40 rows
    const uint4* src = (const uint4*)g_wp + chunk * 896;
    for (int i = tid; i < 896; i += 256) {
        int split = (i >= 448) ? 1 : 0;
        int j = i - split * 448;
        int n = j >> 1, hf = j & 1;
        *(uint4*)(smem + B_OFF + (buf * 2 + split) * B_SZ + n * 80 + hf * 16) = src[i];
    }
    // A: im2col of t, 64 voxels x 16 k, split hi/lo
    const TapS* taps = (const TapS*)(smem + TAP_OFF);
#pragma unroll
    for (int r = 0; r < 4; r++) {
        int idx = tid + r * 256;
        int v = idx & 63, kloc = idx >> 6;
        TapS tp = taps[chunk * 16 + kloc];
        int loc = loc0 + v;
        int h = loc >> 10, w = (loc >> 5) & 31, d = loc & 31;
        float val = 0.f;
        if ((unsigned)(h + tp.dh) < 32u && (unsigned)(w + tp.dw) < 32u &&
            (unsigned)(d + tp.dd) < 32u)
            val = g_t[base_t + loc + tp.delta];
        __nv_bfloat16 hb = __float2bfloat16(val);
        float lo = val - __bfloat162float(hb);
        __nv_bfloat16 lb = __float2bfloat16(lo);
        *(__nv_bfloat16*)(smem + A_OFF + (buf * 2 + 0) * A_SZ + v * 80 + kloc * 2) = hb;
        *(__nv_bfloat16*)(smem + A_OFF + (buf * 2 + 1) * A_SZ + v * 80 + kloc * 2) = lb;
    }
}

__global__ __launch_bounds__(256, 2) void k_enc(const float* __restrict__ b_enc) {
    extern __shared__ __align__(16) char smem[];
    int tid = threadIdx.x;
    if (tid < 224) {
        TapS tp;
        tp.delta = g_tapdelta[tid];
        tp.dh = g_tap_h[tid]; tp.dw = g_tap_w[tid]; tp.dd = g_tap_d[tid];
        ((TapS*)(smem + TAP_OFF))[tid] = tp;
    }
    int gv0 = blockIdx.x * 64;
    int n = gv0 >> 15;
    int loc0 = gv0 & (VOX - 1);
    int base_t = n * 8 * VOX;

    int warp = tid >> 5, lane = tid & 31;
    int warp_m = warp & 1;       // 0..1 -> 32 voxels
    int warp_n = warp >> 1;      // 0..3 -> 56 oc
    int g = lane >> 2, tc = lane & 3;

    __syncthreads();             // taps visible
    stage_chunk(smem, 0, 0, tid, loc0, base_t);
    __syncthreads();

    float acc[14][4];
#pragma unroll
    for (int t = 0; t < 14; t++)
#pragma unroll
        for (int q = 0; q < 4; q++) acc[t][q] = 0.f;

    int buf = 0;
    for (int chunk = 0; chunk < 14; chunk++) {
        if (chunk < 13)
            stage_chunk(smem, buf ^ 1, chunk + 1, tid, loc0, base_t);

        const char* As = smem + A_OFF + (buf * 2) * A_SZ;
        const char* Bs = smem + B_OFF + (buf * 2) * B_SZ;

        u32 ah[2][4], al[2][4];
#pragma unroll
        for (int mt = 0; mt < 2; mt++) {
            int row = warp_m * 32 + mt * 16 + g;
            ah[mt][0] = *(const u32*)(As + row * 80 + tc * 4);
            ah[mt][1] = *(const u32*)(As + (row + 8) * 80 + tc * 4);
            ah[mt][2] = *(const u32*)(As + row * 80 + 16 + tc * 4);
            ah[mt][3] = *(const u32*)(As + (row + 8) * 80 + 16 + tc * 4);
            al[mt][0] = *(const u32*)(As + A_SZ + row * 80 + tc * 4);
            al[mt][1] = *(const u32*)(As + A_SZ + (row + 8) * 80 + tc * 4);
            al[mt][2] = *(const u32*)(As + A_SZ + row * 80 + 16 + tc * 4);
            al[mt][3] = *(const u32*)(As + A_SZ + (row + 8) * 80 + 16 + tc * 4);
        }
#pragma unroll
        for (int nt = 0; nt < 7; nt++) {
            int col = warp_n * 56 + nt * 8 + g;
            u32 bh0 = *(const u32*)(Bs + col * 80 + tc * 4);
            u32 bh1 = *(const u32*)(Bs + col * 80 + 16 + tc * 4);
            u32 bl0 = *(const u32*)(Bs + B_SZ + col * 80 + tc * 4);
            u32 bl1 = *(const u32*)(Bs + B_SZ + col * 80 + 16 + tc * 4);
#pragma unroll
            for (int mt = 0; mt < 2; mt++) {
                int t = mt * 7 + nt;
                MMA_BF16(acc[t], ah[mt], bh0, bh1);
                MMA_BF16(acc[t], ah[mt], bl0, bl1);
                MMA_BF16(acc[t], al[mt], bh0, bh1);
            }
        }
        __syncthreads();
        buf ^= 1;
    }

    // epilogue: D[vox][oc] + b_enc -> g_enc[gv][216]
#pragma unroll
    for (int nt = 0; nt < 7; nt++) {
        if (warp_n == 3 && nt == 6) continue;      // oc 216..223 pad
        int oc = warp_n * 56 + nt * 8 + tc * 2;
        float bx = __ldg(b_enc + oc), by = __ldg(b_enc + oc + 1);
#pragma unroll
        for (int mt = 0; mt < 2; mt++) {
            int t = mt * 7 + nt;
            int r0 = gv0 + warp_m * 32 + mt * 16 + g;
            float* p0 = g_enc + (size_t)r0 * 216 + oc;
            *(float2*)p0 = make_float2(acc[t][0] + bx, acc[t][1] + by);
            *(float2*)(p0 + (size_t)8 * 216) = make_float2(acc[t][2] + bx, acc[t][3] + by);
        }
    }
}

// ---------------- k_out: softmax + reassembly + pixel shuffle + bias ----------------
// One thread per coarse voxel (R2 version, measured fastest).
__global__ __launch_bounds__(256) void k_out(const float* __restrict__ b_out,
                                             float* __restrict__ out)
{
    int gv = blockIdx.x * 256 + threadIdx.x;
    int n = gv >> 15;
    int loc = gv & (VOX - 1);
    int h = loc >> 10, w = (loc >> 5) & 31, d = loc & 31;

    const float* erow = g_enc + (size_t)gv * 216;
    const float* zb = g_z + n * 16 * VOX;

    ull acc[16][4];
#pragma unroll
    for (int c = 0; c < 16; c++)
#pragma unroll
        for (int q = 0; q < 4; q++) acc[c][q] = 0ull;
    float Z[8];
#pragma unroll
    for (int r = 0; r < 8; r++) Z[r] = 0.f;

#pragma unroll
    for (int k = 0; k < 27; k++) {
        const int th = k / 9 - 1;
        const int tw = (k / 3) % 3 - 1;
        const int td = k % 3 - 1;
        int hh = h + th, ww = w + tw, dd = d + td;
        bool ok = ((unsigned)hh < 32u) && ((unsigned)ww < 32u) && ((unsigned)dd < 32u);
        int zoff = (hh << 10) + (ww << 5) + dd;

        float4 e0 = *(const float4*)(erow + k * 8);
        float4 e1 = *(const float4*)(erow + k * 8 + 4);
        float p0 = __expf(e0.x), p1 = __expf(e0.y), p2 = __expf(e0.z), p3 = __expf(e0.w);
        float p4 = __expf(e1.x), p5 = __expf(e1.y), p6 = __expf(e1.z), p7 = __expf(e1.w);
        Z[0] += p0; Z[1] += p1; Z[2] += p2; Z[3] += p3;
        Z[4] += p4; Z[5] += p5; Z[6] += p6; Z[7] += p7;
        ull kr0 = pack2(p0, p1), kr1 = pack2(p2, p3);
        ull kr2 = pack2(p4, p5), kr3 = pack2(p6, p7);

#pragma unroll
        for (int c = 0; c < 16; c++) {
            float zv = ok ? __ldg(zb + c * VOX + zoff) : 0.f;
            ull z2 = dup2(zv);
            acc[c][0] = ffma2(kr0, z2, acc[c][0]);
            acc[c][1] = ffma2(kr1, z2, acc[c][1]);
            acc[c][2] = ffma2(kr2, z2, acc[c][2]);
            acc[c][3] = ffma2(kr3, z2, acc[c][3]);
        }
    }

    ull iz[4];
    {
        iz[0] = pack2(1.f / Z[0], 1.f / Z[1]);
        iz[1] = pack2(1.f / Z[2], 1.f / Z[3]);
        iz[2] = pack2(1.f / Z[4], 1.f / Z[5]);
        iz[3] = pack2(1.f / Z[6], 1.f / Z[7]);
    }

#pragma unroll
    for (int c = 0; c < 16; c++) {
        ull b2 = dup2(b_out[c]);
        int cbase = (n * 16 + c) * 64;
#pragma unroll
        for (int q = 0; q < 4; q++) {
            int rh = q >> 1, rw = q & 1;
            ull res = ffma2(acc[c][q], iz[q], b2);
            int addr = (((cbase + h * 2 + rh) * 64) + (w * 2 + rw)) * 64 + d * 2;
            *(ull*)(out + addr) = res;
        }
    }
}

extern "C" void kernel_launch(void* const* d_in, const int* in_sizes, int n_in,
                              void* d_out, int out_size) {
    const float* x      = (const float*)d_in[0];
    const float* w_down = (const float*)d_in[1];
    const float* b_down = (const float*)d_in[2];
    const float* w_enc  = (const float*)d_in[3];
    const float* b_enc  = (const float*)d_in[4];
    const float* w_out  = (const float*)d_in[5];
    const float* b_out  = (const float*)d_in[6];
    float* out = (float*)d_out;

    cudaFuncSetAttribute(k_enc, cudaFuncAttributeMaxDynamicSharedMemorySize, SMEM_ENC);

    k_prep<<<(224 * 224 + 255) / 256, 256>>>(w_enc);
    k_down<<<GV_TOTAL / 256, 256>>>(x, w_down, b_down, w_out);
    k_enc<<<GV_TOTAL / 64, 256, SMEM_ENC>>>(b_enc);
    k_out<<<GV_TOTAL / 256, 256>>>(b_out, out);
}

// round 7
// speedup vs baseline: 1.9340x; 1.1335x over previous
#include <cuda_runtime.h>
#include <cuda_bf16.h>
#include <cstdint>

// CARAFE3D: x[2,32,32,32,32] -> out[2,16,64,64,64]
//   k_prep: W_enc -> bf16 hi/lo split in mma-fragment-major layout; tap tables
//   k_down: t = W_down@x + b_down (8ch), z = W_out@x (16ch)
//   k_enc : persistent; W resident in smem; enc = W @ im2col(t) + b_enc (3-pass bf16)
//   k_out : q-split softmax + reassembly + pixel shuffle + b_out
typedef unsigned long long ull;
typedef unsigned int u32;

#define VOX 32768
#define GV_TOTAL 65536
#define NTILES 1024            // 64 voxels per tile

__device__ float g_t[2 * 8 * VOX];
__device__ float g_z[2 * 16 * VOX];
__device__ __align__(16) uint4 g_wfrag[12544];   // [chunk14][ntg28][lane32] = {bh0,bh1,bl0,bl1}
__device__ float g_enc[(size_t)GV_TOTAL * 216];
__device__ int g_tapdelta[224];
__device__ int g_tap_h[224];
__device__ int g_tap_w[224];
__device__ int g_tap_d[224];

__device__ __forceinline__ ull dup2(float a) {
    ull r; unsigned u = __float_as_uint(a);
    asm("mov.b64 %0, {%1, %1};" : "=l"(r) : "r"(u));
    return r;
}
__device__ __forceinline__ ull pack2(float a, float b) {
    ull r;
    asm("mov.b64 %0, {%1, %2};" : "=l"(r) : "r"(__float_as_uint(a)), "r"(__float_as_uint(b)));
    return r;
}
__device__ __forceinline__ ull ffma2(ull a, ull b, ull c) {
    ull d;
    asm("fma.rn.f32x2 %0, %1, %2, %3;" : "=l"(d) : "l"(a), "l"(b), "l"(c));
    return d;
}
#define MMA_BF16(d, a, b0_, b1_) \
    asm volatile("mma.sync.aligned.m16n8k16.row.col.f32.bf16.bf16.f32 " \
        "{%0,%1,%2,%3}, {%4,%5,%6,%7}, {%8,%9}, {%0,%1,%2,%3};" \
        : "+f"((d)[0]), "+f"((d)[1]), "+f"((d)[2]), "+f"((d)[3]) \
        : "r"((a)[0]), "r"((a)[1]), "r"((a)[2]), "r"((a)[3]), "r"(b0_), "r"(b1_))

__device__ __forceinline__ unsigned short bf16bits(float v) {
    __nv_bfloat16 b = __float2bfloat16(v);
    return *(unsigned short*)&b;
}
__device__ __forceinline__ float bf16val(unsigned short s) {
    __nv_bfloat16 b = *(__nv_bfloat16*)&s;
    return __bfloat162float(b);
}

// ---------------- k_prep: W fragments + tap tables ----------------
__global__ void k_prep(const float* __restrict__ w_enc) {
    int i = blockIdx.x * 256 + threadIdx.x;
    if (i < 12544) {
        int chunk = i / 896;
        int rem = i - chunk * 896;
        int ntg = rem >> 5;
        int lane = rem & 31;
        int g = lane >> 2, tc = lane & 3;
        int oc = ntg * 8 + g;
        int kb = chunk * 16;
        int ks[4] = { kb + 2 * tc, kb + 2 * tc + 1, kb + 8 + 2 * tc, kb + 9 + 2 * tc };
        float v[4];
#pragma unroll
        for (int j = 0; j < 4; j++)
            v[j] = (oc < 216 && ks[j] < 216) ? w_enc[oc * 216 + ks[j]] : 0.f;
        unsigned short h[4], l[4];
#pragma unroll
        for (int j = 0; j < 4; j++) {
            h[j] = bf16bits(v[j]);
            l[j] = bf16bits(v[j] - bf16val(h[j]));
        }
        uint4 q;
        q.x = (u32)h[0] | ((u32)h[1] << 16);   // hi b0
        q.y = (u32)h[2] | ((u32)h[3] << 16);   // hi b1
        q.z = (u32)l[0] | ((u32)l[1] << 16);   // lo b0
        q.w = (u32)l[2] | ((u32)l[3] << 16);   // lo b1
        g_wfrag[i] = q;
    }
    if (i < 224) {
        if (i < 216) {
            int ci = i / 27;
            int tap = i - ci * 27;
            int th = tap / 9;
            int tr = tap - th * 9;
            int tw = tr / 3;
            int td = tr - tw * 3;
            g_tapdelta[i] = ci * VOX + (th - 1) * 1024 + (tw - 1) * 32 + (td - 1);
            g_tap_h[i] = th - 1; g_tap_w[i] = tw - 1; g_tap_d[i] = td - 1;
        } else {
            g_tapdelta[i] = 0; g_tap_h[i] = 99; g_tap_w[i] = 99; g_tap_d[i] = 99;
        }
    }
}

// ---------------- k_down ----------------
__global__ __launch_bounds__(256) void k_down(
    const float* __restrict__ x,
    const float* __restrict__ wd, const float* __restrict__ bd,
    const float* __restrict__ wo)
{
    __shared__ float swd[8 * 32];
    __shared__ float swo[16 * 32];
    int tid = threadIdx.x;
    if (tid < 256) swd[tid] = wd[tid];
    swo[tid] = wo[tid];
    swo[tid + 256] = wo[tid + 256];
    __syncthreads();

    int gv = blockIdx.x * 256 + tid;
    int n = gv >> 15;
    int loc = gv & (VOX - 1);
    const float* xb = x + n * (32 * VOX) + loc;

    float xv[32];
#pragma unroll
    for (int c = 0; c < 32; c++) xv[c] = xb[c * VOX];
#pragma unroll
    for (int m = 0; m < 8; m++) {
        float acc = bd[m];
#pragma unroll
        for (int c = 0; c < 32; c++) acc += swd[m * 32 + c] * xv[c];
        g_t[(n * 8 + m) * VOX + loc] = acc;
    }
#pragma unroll
    for (int m = 0; m < 16; m++) {
        float acc = 0.f;
#pragma unroll
        for (int c = 0; c < 32; c++) acc += swo[m * 32 + c] * xv[c];
        g_z[(n * 16 + m) * VOX + loc] = acc;
    }
}

// ---------------- k_enc: persistent, W-resident, fragment-major ----------------
// Smem: [0, 200704) W frags; [200704, +8192) A frags (2 bufs x {hi 2048B, lo 2048B});
//       [208896, +3584) taps.
struct TapS { int delta, dh, dw, dd; };
#define W_OFF 0
#define A_OFF 200704
#define A_BUFSZ 4096
#define TAP_OFF 208896
#define SMEM_ENC 212480

// Stage A chunk (64 vox x 16 k, hi/lo) in fragment-major layout.
// Thread tid handles fragment words f0=2*tid, f0+1 (same (g,tc,j), voxels v and v+8).
__device__ __forceinline__ void stage_a(
    char* smem, int buf, int chunk, int tid, int loc0, int base_t)
{
    const TapS* taps = (const TapS*)(smem + TAP_OFF);
    int f0 = tid * 2;
    int w0 = f0 & 3;                 // 0 or 2
    int lane = (f0 >> 2) & 31;
    int G = f0 >> 7;
    int g = lane >> 2, tc = lane & 3;
    int j = (w0 >> 1) * 4 + tc;      // 0..7
    int k0 = chunk * 16 + 2 * j;
    int va = G * 16 + g;
    TapS t0 = taps[k0];
    TapS t1 = taps[k0 + 1];

    float vals[4];                   // [v(a,b)][k(0,1)]
#pragma unroll
    for (int s = 0; s < 2; s++) {
        int loc = loc0 + va + s * 8;
        int h = loc >> 10, w = (loc >> 5) & 31, d = loc & 31;
        float v0 = 0.f, v1 = 0.f;
        if ((unsigned)(h + t0.dh) < 32u && (unsigned)(w + t0.dw) < 32u &&
            (unsigned)(d + t0.dd) < 32u)
            v0 = g_t[base_t + loc + t0.delta];
        if ((unsigned)(h + t1.dh) < 32u && (unsigned)(w + t1.dw) < 32u &&
            (unsigned)(d + t1.dd) < 32u)
            v1 = g_t[base_t + loc + t1.delta];
        vals[s * 2] = v0; vals[s * 2 + 1] = v1;
    }
    unsigned short hb[4], lb[4];
#pragma unroll
    for (int q = 0; q < 4; q++) {
        hb[q] = bf16bits(vals[q]);
        lb[q] = bf16bits(vals[q] - bf16val(hb[q]));
    }
    u32 hwa = (u32)hb[0] | ((u32)hb[1] << 16);
    u32 hwb = (u32)hb[2] | ((u32)hb[3] << 16);
    u32 lwa = (u32)lb[0] | ((u32)lb[1] << 16);
    u32 lwb = (u32)lb[2] | ((u32)lb[3] << 16);
    char* ab = smem + A_OFF + buf * A_BUFSZ;
    *(ull*)(ab + f0 * 4) = pack2(__uint_as_float(hwa), __uint_as_float(hwb));
    *(ull*)(ab + 2048 + f0 * 4) = pack2(__uint_as_float(lwa), __uint_as_float(lwb));
}

__global__ __launch_bounds__(256, 1) void k_enc(const float* __restrict__ b_enc) {
    extern __shared__ __align__(16) char smem[];
    int tid = threadIdx.x;

    // resident weights + taps
    {
        uint4* wd = (uint4*)(smem + W_OFF);
        for (int i = tid; i < 12544; i += 256) wd[i] = g_wfrag[i];
    }
    if (tid < 224) {
        TapS tp;
        tp.delta = g_tapdelta[tid];
        tp.dh = g_tap_h[tid]; tp.dw = g_tap_w[tid]; tp.dd = g_tap_d[tid];
        ((TapS*)(smem + TAP_OFF))[tid] = tp;
    }
    __syncthreads();

    int warp = tid >> 5, lane = tid & 31;
    int warp_m = warp & 3;           // 16 voxels each
    int warp_n = warp >> 2;          // 112 oc each
    int g = lane >> 2, tc = lane & 3;

    for (int tile = blockIdx.x; tile < NTILES; tile += 148) {
        int gv0 = tile * 64;
        int n = gv0 >> 15;
        int loc0 = gv0 & (VOX - 1);
        int base_t = n * 8 * VOX;

        stage_a(smem, 0, 0, tid, loc0, base_t);
        __syncthreads();

        float acc[14][4];
#pragma unroll
        for (int t = 0; t < 14; t++)
#pragma unroll
            for (int q = 0; q < 4; q++) acc[t][q] = 0.f;

        int buf = 0;
        for (int chunk = 0; chunk < 14; chunk++) {
            if (chunk < 13)
                stage_a(smem, buf ^ 1, chunk + 1, tid, loc0, base_t);

            const char* ab = smem + A_OFF + buf * A_BUFSZ;
            uint4 ahv = *(const uint4*)(ab + (warp_m * 32 + lane) * 16);
            uint4 alv = *(const uint4*)(ab + 2048 + (warp_m * 32 + lane) * 16);
            u32 ah[4] = { ahv.x, ahv.y, ahv.z, ahv.w };
            u32 al[4] = { alv.x, alv.y, alv.z, alv.w };

#pragma unroll
            for (int nt = 0; nt < 14; nt++) {
                int ntg = warp_n * 14 + nt;
                uint4 wf = *(const uint4*)(smem + W_OFF +
                                           ((chunk * 28 + ntg) * 32 + lane) * 16);
                MMA_BF16(acc[nt], ah, wf.x, wf.y);   // Ah * Wh
                MMA_BF16(acc[nt], ah, wf.z, wf.w);   // Ah * Wl
                MMA_BF16(acc[nt], al, wf.x, wf.y);   // Al * Wh
            }
            __syncthreads();
            buf ^= 1;
        }

        // epilogue: +bias -> g_enc[gv][216] (oc 216..223 are pad -> ntg 27 skipped)
#pragma unroll
        for (int nt = 0; nt < 14; nt++) {
            int ntg = warp_n * 14 + nt;
            if (ntg == 27) continue;
            int oc = ntg * 8 + tc * 2;
            float bx = __ldg(b_enc + oc), by = __ldg(b_enc + oc + 1);
            int v0 = gv0 + warp_m * 16 + g;
            float* p0 = g_enc + (size_t)v0 * 216 + oc;
            *(float2*)p0 = make_float2(acc[nt][0] + bx, acc[nt][1] + by);
            *(float2*)(p0 + (size_t)8 * 216) = make_float2(acc[nt][2] + bx, acc[nt][3] + by);
        }
    }
}

// ---------------- k_out: q-split softmax + reassembly + pixel shuffle ----------------
// 2 threads per voxel: qh=0 handles r 0..3 (q 0,1), qh=1 handles r 4..7 (q 2,3).
__global__ __launch_bounds__(256, 2) void k_out(const float* __restrict__ b_out,
                                                float* __restrict__ out)
{
    int tid = threadIdx.x;
    int vloc = tid & 127;
    int qh = tid >> 7;
    int gv = blockIdx.x * 128 + vloc;
    int n = gv >> 15;
    int loc = gv & (VOX - 1);
    int h = loc >> 10, w = (loc >> 5) & 31, d = loc & 31;

    const float* erow = g_enc + (size_t)gv * 216 + qh * 4;
    const float* zb = g_z + n * 16 * VOX;

    ull acc[16][2];
#pragma unroll
    for (int c = 0; c < 16; c++) { acc[c][0] = 0ull; acc[c][1] = 0ull; }
    float Z0 = 0.f, Z1 = 0.f, Z2 = 0.f, Z3 = 0.f;

#pragma unroll
    for (int k = 0; k < 27; k++) {
        const int th = k / 9 - 1;
        const int tw = (k / 3) % 3 - 1;
        const int td = k % 3 - 1;
        int hh = h + th, ww = w + tw, dd = d + td;
        bool ok = ((unsigned)hh < 32u) && ((unsigned)ww < 32u) && ((unsigned)dd < 32u);
        int zoff = (hh << 10) + (ww << 5) + dd;

        float4 e = *(const float4*)(erow + k * 8);
        float p0 = __expf(e.x), p1 = __expf(e.y), p2 = __expf(e.z), p3 = __expf(e.w);
        Z0 += p0; Z1 += p1; Z2 += p2; Z3 += p3;
        ull kr0 = pack2(p0, p1), kr1 = pack2(p2, p3);

#pragma unroll
        for (int c = 0; c < 16; c++) {
            float zv = ok ? __ldg(zb + c * VOX + zoff) : 0.f;
            ull z2 = dup2(zv);
            acc[c][0] = ffma2(kr0, z2, acc[c][0]);
            acc[c][1] = ffma2(kr1, z2, acc[c][1]);
        }
    }

    ull iz0 = pack2(1.f / Z0, 1.f / Z1);
    ull iz1 = pack2(1.f / Z2, 1.f / Z3);

#pragma unroll
    for (int c = 0; c < 16; c++) {
        ull b2 = dup2(b_out[c]);
        int cbase = (n * 16 + c) * 64;
#pragma unroll
        for (int jq = 0; jq < 2; jq++) {
            int q = qh * 2 + jq;
            int rh = q >> 1, rw = q & 1;
            ull res = ffma2(jq ? acc[c][1] : acc[c][0], jq ? iz1 : iz0, b2);
            int addr = (((cbase + h * 2 + rh) * 64) + (w * 2 + rw)) * 64 + d * 2;
            *(ull*)(out + addr) = res;
        }
    }
}

extern "C" void kernel_launch(void* const* d_in, const int* in_sizes, int n_in,
                              void* d_out, int out_size) {
    const float* x      = (const float*)d_in[0];
    const float* w_down = (const float*)d_in[1];
    const float* b_down = (const float*)d_in[2];
    const float* w_enc  = (const float*)d_in[3];
    const float* b_enc  = (const float*)d_in[4];
    const float* w_out  = (const float*)d_in[5];
    const float* b_out  = (const float*)d_in[6];
    float* out = (float*)d_out;

    cudaFuncSetAttribute(k_enc, cudaFuncAttributeMaxDynamicSharedMemorySize, SMEM_ENC);

    k_prep<<<49, 256>>>(w_enc);
    k_down<<<GV_TOTAL / 256, 256>>>(x, w_down, b_down, w_out);
    k_enc<<<148, 256, SMEM_ENC>>>(b_enc);
    k_out<<<GV_TOTAL / 128, 256>>>(b_out, out);
}

// round 8
// speedup vs baseline: 2.7309x; 1.4121x over previous
#include <cuda_runtime.h>
#include <cuda_fp16.h>
#include <cstdint>

// CARAFE3D: x[2,32,32,32,32] -> out[2,16,64,64,64]
//   k_prep: W_enc -> single fp16, mma-fragment-major; tap tables
//   k_down: t = W_down@x + b_down (8ch), z = W_out@x (16ch)
//   k_enc : persistent, 2 CTA/SM; W resident; enc_T[oc][gv] = W@im2col(t)+b_enc
//           via fp16 mma.sync 2-pass A-split (Ah*W + Al*W)
//   k_out : q-split softmax + reassembly + pixel shuffle + b_out (coalesced enc_T)
typedef unsigned long long ull;
typedef unsigned int u32;

#define VOX 32768
#define GV_TOTAL 65536
#define NTILES 1024            // 64 voxels per tile

__device__ float g_t[2 * 8 * VOX];
__device__ float g_z[2 * 16 * VOX];
__device__ __align__(16) uint2 g_wfrag[12544];   // [chunk14][ntg28][lane32] = {b0,b1} fp16
__device__ float g_enc[(size_t)216 * GV_TOTAL];  // TRANSPOSED: [oc][gv]
__device__ int g_tapdelta[224];
__device__ int g_tap_h[224];
__device__ int g_tap_w[224];
__device__ int g_tap_d[224];

__device__ __forceinline__ ull dup2(float a) {
    ull r; unsigned u = __float_as_uint(a);
    asm("mov.b64 %0, {%1, %1};" : "=l"(r) : "r"(u));
    return r;
}
__device__ __forceinline__ ull pack2(float a, float b) {
    ull r;
    asm("mov.b64 %0, {%1, %2};" : "=l"(r) : "r"(__float_as_uint(a)), "r"(__float_as_uint(b)));
    return r;
}
__device__ __forceinline__ ull ffma2(ull a, ull b, ull c) {
    ull d;
    asm("fma.rn.f32x2 %0, %1, %2, %3;" : "=l"(d) : "l"(a), "l"(b), "l"(c));
    return d;
}
#define MMA_F16(d, a, b0_, b1_) \
    asm volatile("mma.sync.aligned.m16n8k16.row.col.f32.f16.f16.f32 " \
        "{%0,%1,%2,%3}, {%4,%5,%6,%7}, {%8,%9}, {%0,%1,%2,%3};" \
        : "+f"((d)[0]), "+f"((d)[1]), "+f"((d)[2]), "+f"((d)[3]) \
        : "r"((a)[0]), "r"((a)[1]), "r"((a)[2]), "r"((a)[3]), "r"(b0_), "r"(b1_))

__device__ __forceinline__ unsigned short f16bits(float v) {
    __half h = __float2half_rn(v);
    return *(unsigned short*)&h;
}
__device__ __forceinline__ float f16val(unsigned short s) {
    __half h = *(__half*)&s;
    return __half2float(h);
}

// ---------------- k_prep: W fragments (fp16) + tap tables ----------------
__global__ void k_prep(const float* __restrict__ w_enc) {
    int i = blockIdx.x * 256 + threadIdx.x;
    if (i < 12544) {
        int chunk = i / 896;
        int rem = i - chunk * 896;
        int ntg = rem >> 5;
        int lane = rem & 31;
        int g = lane >> 2, tc = lane & 3;
        int oc = ntg * 8 + g;
        int kb = chunk * 16;
        int ks[4] = { kb + 2 * tc, kb + 2 * tc + 1, kb + 8 + 2 * tc, kb + 9 + 2 * tc };
        unsigned short hh[4];
#pragma unroll
        for (int j = 0; j < 4; j++) {
            float v = (oc < 216 && ks[j] < 216) ? w_enc[oc * 216 + ks[j]] : 0.f;
            hh[j] = f16bits(v);
        }
        uint2 q;
        q.x = (u32)hh[0] | ((u32)hh[1] << 16);
        q.y = (u32)hh[2] | ((u32)hh[3] << 16);
        g_wfrag[i] = q;
    }
    if (i < 224) {
        if (i < 216) {
            int ci = i / 27;
            int tap = i - ci * 27;
            int th = tap / 9;
            int tr = tap - th * 9;
            int tw = tr / 3;
            int td = tr - tw * 3;
            g_tapdelta[i] = ci * VOX + (th - 1) * 1024 + (tw - 1) * 32 + (td - 1);
            g_tap_h[i] = th - 1; g_tap_w[i] = tw - 1; g_tap_d[i] = td - 1;
        } else {
            g_tapdelta[i] = 0; g_tap_h[i] = 99; g_tap_w[i] = 99; g_tap_d[i] = 99;
        }
    }
}

// ---------------- k_down ----------------
__global__ __launch_bounds__(256) void k_down(
    const float* __restrict__ x,
    const float* __restrict__ wd, const float* __restrict__ bd,
    const float* __restrict__ wo)
{
    __shared__ float swd[8 * 32];
    __shared__ float swo[16 * 32];
    int tid = threadIdx.x;
    if (tid < 256) swd[tid] = wd[tid];
    swo[tid] = wo[tid];
    swo[tid + 256] = wo[tid + 256];
    __syncthreads();

    int gv = blockIdx.x * 256 + tid;
    int n = gv >> 15;
    int loc = gv & (VOX - 1);
    const float* xb = x + n * (32 * VOX) + loc;

    float xv[32];
#pragma unroll
    for (int c = 0; c < 32; c++) xv[c] = xb[c * VOX];
#pragma unroll
    for (int m = 0; m < 8; m++) {
        float acc = bd[m];
#pragma unroll
        for (int c = 0; c < 32; c++) acc += swd[m * 32 + c] * xv[c];
        g_t[(n * 8 + m) * VOX + loc] = acc;
    }
#pragma unroll
    for (int m = 0; m < 16; m++) {
        float acc = 0.f;
#pragma unroll
        for (int c = 0; c < 32; c++) acc += swo[m * 32 + c] * xv[c];
        g_z[(n * 16 + m) * VOX + loc] = acc;
    }
}

// ---------------- k_enc: persistent, 2 CTA/SM, W-resident fp16 ----------------
// Smem: [0, 100352) W frags; [100352, +8192) A frags (2 bufs x {hi 2048, lo 2048});
//       [108544, +3584) taps.  Total 112128 -> 2 CTAs/SM.
struct TapS { int delta, dh, dw, dd; };
#define W_OFF 0
#define A_OFF 100352
#define A_BUFSZ 4096
#define TAP_OFF 108544
#define SMEM_ENC 112128

// Stage A chunk (64 vox x 16 k, fp16 hi/lo) in fragment-major layout.
__device__ __forceinline__ void stage_a(
    char* smem, int buf, int chunk, int tid, int loc0, int base_t)
{
    const TapS* taps = (const TapS*)(smem + TAP_OFF);
    int f0 = tid * 2;
    int w0 = f0 & 3;                 // 0 or 2
    int lane = (f0 >> 2) & 31;
    int G = f0 >> 7;
    int g = lane >> 2, tc = lane & 3;
    int j = (w0 >> 1) * 4 + tc;      // 0..7
    int k0 = chunk * 16 + 2 * j;
    int va = G * 16 + g;
    TapS t0 = taps[k0];
    TapS t1 = taps[k0 + 1];

    float vals[4];                   // [v(a,b)][k(0,1)]
#pragma unroll
    for (int s = 0; s < 2; s++) {
        int loc = loc0 + va + s * 8;
        int h = loc >> 10, w = (loc >> 5) & 31, d = loc & 31;
        float v0 = 0.f, v1 = 0.f;
        if ((unsigned)(h + t0.dh) < 32u && (unsigned)(w + t0.dw) < 32u &&
            (unsigned)(d + t0.dd) < 32u)
            v0 = g_t[base_t + loc + t0.delta];
        if ((unsigned)(h + t1.dh) < 32u && (unsigned)(w + t1.dw) < 32u &&
            (unsigned)(d + t1.dd) < 32u)
            v1 = g_t[base_t + loc + t1.delta];
        vals[s * 2] = v0; vals[s * 2 + 1] = v1;
    }
    unsigned short hb[4], lb[4];
#pragma unroll
    for (int q = 0; q < 4; q++) {
        hb[q] = f16bits(vals[q]);
        lb[q] = f16bits(vals[q] - f16val(hb[q]));
    }
    u32 hwa = (u32)hb[0] | ((u32)hb[1] << 16);
    u32 hwb = (u32)hb[2] | ((u32)hb[3] << 16);
    u32 lwa = (u32)lb[0] | ((u32)lb[1] << 16);
    u32 lwb = (u32)lb[2] | ((u32)lb[3] << 16);
    char* ab = smem + A_OFF + buf * A_BUFSZ;
    *(ull*)(ab + f0 * 4) = pack2(__uint_as_float(hwa), __uint_as_float(hwb));
    *(ull*)(ab + 2048 + f0 * 4) = pack2(__uint_as_float(lwa), __uint_as_float(lwb));
}

__global__ __launch_bounds__(256, 2) void k_enc(const float* __restrict__ b_enc) {
    extern __shared__ __align__(16) char smem[];
    int tid = threadIdx.x;

    // resident weights + taps
    {
        uint2* wd = (uint2*)(smem + W_OFF);
        for (int i = tid; i < 12544; i += 256) wd[i] = g_wfrag[i];
    }
    if (tid < 224) {
        TapS tp;
        tp.delta = g_tapdelta[tid];
        tp.dh = g_tap_h[tid]; tp.dw = g_tap_w[tid]; tp.dd = g_tap_d[tid];
        ((TapS*)(smem + TAP_OFF))[tid] = tp;
    }
    __syncthreads();

    int warp = tid >> 5, lane = tid & 31;
    int warp_m = warp & 3;           // 16 voxels each
    int warp_n = warp >> 2;          // 112 oc each
    int g = lane >> 2, tc = lane & 3;

    for (int tile = blockIdx.x; tile < NTILES; tile += gridDim.x) {
        int gv0 = tile * 64;
        int n = gv0 >> 15;
        int loc0 = gv0 & (VOX - 1);
        int base_t = n * 8 * VOX;

        stage_a(smem, 0, 0, tid, loc0, base_t);
        __syncthreads();

        float acc[14][4];
#pragma unroll
        for (int t = 0; t < 14; t++)
#pragma unroll
            for (int q = 0; q < 4; q++) acc[t][q] = 0.f;

        int buf = 0;
        for (int chunk = 0; chunk < 14; chunk++) {
            if (chunk < 13)
                stage_a(smem, buf ^ 1, chunk + 1, tid, loc0, base_t);

            const char* ab = smem + A_OFF + buf * A_BUFSZ;
            uint4 ahv = *(const uint4*)(ab + (warp_m * 32 + lane) * 16);
            uint4 alv = *(const uint4*)(ab + 2048 + (warp_m * 32 + lane) * 16);
            u32 ah[4] = { ahv.x, ahv.y, ahv.z, ahv.w };
            u32 al[4] = { alv.x, alv.y, alv.z, alv.w };

#pragma unroll
            for (int nt = 0; nt < 14; nt++) {
                int ntg = warp_n * 14 + nt;
                uint2 wf = *(const uint2*)(smem + W_OFF +
                                           ((chunk * 28 + ntg) * 32 + lane) * 8);
                MMA_F16(acc[nt], ah, wf.x, wf.y);    // Ah * W
                MMA_F16(acc[nt], al, wf.x, wf.y);    // Al * W
            }
            __syncthreads();
            buf ^= 1;
        }

        // epilogue: +bias -> enc_T[oc][gv]  (ntg 27 is pad)
#pragma unroll
        for (int nt = 0; nt < 14; nt++) {
            int ntg = warp_n * 14 + nt;
            if (ntg == 27) continue;
            int oc = ntg * 8 + tc * 2;
            float bx = __ldg(b_enc + oc), by = __ldg(b_enc + oc + 1);
            int v0 = gv0 + warp_m * 16 + g;
            float* p0 = g_enc + (size_t)oc * GV_TOTAL + v0;
            p0[0] = acc[nt][0] + bx;
            p0[GV_TOTAL] = acc[nt][1] + by;
            p0[8] = acc[nt][2] + bx;
            p0[GV_TOTAL + 8] = acc[nt][3] + by;
        }
    }
}

// ---------------- k_out: q-split softmax + reassembly + pixel shuffle ----------------
// 2 threads per voxel: qh=0 handles r 0..3 (q 0,1), qh=1 handles r 4..7 (q 2,3).
// enc_T[oc][gv] -> per-tap 4 lane-coalesced scalar loads.
__global__ __launch_bounds__(256, 2) void k_out(const float* __restrict__ b_out,
                                                float* __restrict__ out)
{
    int tid = threadIdx.x;
    int vloc = tid & 127;
    int qh = tid >> 7;
    int gv = blockIdx.x * 128 + vloc;
    int n = gv >> 15;
    int loc = gv & (VOX - 1);
    int h = loc >> 10, w = (loc >> 5) & 31, d = loc & 31;

    const float* erow = g_enc + (size_t)(qh * 4) * GV_TOTAL + gv;
    const float* zb = g_z + n * 16 * VOX;

    ull acc[16][2];
#pragma unroll
    for (int c = 0; c < 16; c++) { acc[c][0] = 0ull; acc[c][1] = 0ull; }
    float Z0 = 0.f, Z1 = 0.f, Z2 = 0.f, Z3 = 0.f;

#pragma unroll
    for (int k = 0; k < 27; k++) {
        const int th = k / 9 - 1;
        const int tw = (k / 3) % 3 - 1;
        const int td = k % 3 - 1;
        int hh = h + th, ww = w + tw, dd = d + td;
        bool ok = ((unsigned)hh < 32u) && ((unsigned)ww < 32u) && ((unsigned)dd < 32u);
        int zoff = (hh << 10) + (ww << 5) + dd;

        float e0 = __ldg(erow + (size_t)(k * 8 + 0) * GV_TOTAL);
        float e1 = __ldg(erow + (size_t)(k * 8 + 1) * GV_TOTAL);
        float e2 = __ldg(erow + (size_t)(k * 8 + 2) * GV_TOTAL);
        float e3 = __ldg(erow + (size_t)(k * 8 + 3) * GV_TOTAL);
        float p0 = __expf(e0), p1 = __expf(e1), p2 = __expf(e2), p3 = __expf(e3);
        Z0 += p0; Z1 += p1; Z2 += p2; Z3 += p3;
        ull kr0 = pack2(p0, p1), kr1 = pack2(p2, p3);

#pragma unroll
        for (int c = 0; c < 16; c++) {
            float zv = ok ? __ldg(zb + c * VOX + zoff) : 0.f;
            ull z2 = dup2(zv);
            acc[c][0] = ffma2(kr0, z2, acc[c][0]);
            acc[c][1] = ffma2(kr1, z2, acc[c][1]);
        }
    }

    ull iz0 = pack2(1.f / Z0, 1.f / Z1);
    ull iz1 = pack2(1.f / Z2, 1.f / Z3);

#pragma unroll
    for (int c = 0; c < 16; c++) {
        ull b2 = dup2(b_out[c]);
        int cbase = (n * 16 + c) * 64;
#pragma unroll
        for (int jq = 0; jq < 2; jq++) {
            int q = qh * 2 + jq;
            int rh = q >> 1, rw = q & 1;
            ull res = ffma2(jq ? acc[c][1] : acc[c][0], jq ? iz1 : iz0, b2);
            int addr = (((cbase + h * 2 + rh) * 64) + (w * 2 + rw)) * 64 + d * 2;
            *(ull*)(out + addr) = res;
        }
    }
}

extern "C" void kernel_launch(void* const* d_in, const int* in_sizes, int n_in,
                              void* d_out, int out_size) {
    const float* x      = (const float*)d_in[0];
    const float* w_down = (const float*)d_in[1];
    const float* b_down = (const float*)d_in[2];
    const float* w_enc  = (const float*)d_in[3];
    const float* b_enc  = (const float*)d_in[4];
    const float* w_out  = (const float*)d_in[5];
    const float* b_out  = (const float*)d_in[6];
    float* out = (float*)d_out;

    cudaFuncSetAttribute(k_enc, cudaFuncAttributeMaxDynamicSharedMemorySize, SMEM_ENC);

    k_prep<<<49, 256>>>(w_enc);
    k_down<<<GV_TOTAL / 256, 256>>>(x, w_down, b_down, w_out);
    k_enc<<<296, 256, SMEM_ENC>>>(b_enc);
    k_out<<<GV_TOTAL / 128, 256>>>(b_out, out);
}

// round 9
// speedup vs baseline: 2.7415x; 1.0039x over previous
#include <cuda_runtime.h>
#include <cuda_fp16.h>
#include <cstdint>

// CARAFE3D: x[2,32,32,32,32] -> out[2,16,64,64,64]
//   k_prep: W_enc -> fp16 mma-fragment-major; tap tables
//   k_down: t = W_down@x + b_down (8ch planar), z = W_out@x ([loc][16c] interleaved)
//   k_enc : persistent, 2 CTA/SM; W resident; single-pass fp16 mma.sync;
//           enc packed [k*2+qh][gv][4r]
//   k_out : q-split softmax + reassembly + pixel shuffle + b_out (vector loads)
typedef unsigned long long ull;
typedef unsigned int u32;

#define VOX 32768
#define GV_TOTAL 65536
#define NTILES 1024            // 64 voxels per tile

__device__ float g_t[2 * 8 * VOX];
__device__ __align__(16) float g_z[2 * VOX * 16];       // [n][loc][c]
__device__ __align__(16) uint2 g_wfrag[12544];          // [chunk14][ntg28][lane32]
__device__ __align__(16) float g_enc[(size_t)216 * GV_TOTAL];  // [54 grp][gv][4]
__device__ int g_tapdelta[224];
__device__ int g_tap_h[224];
__device__ int g_tap_w[224];
__device__ int g_tap_d[224];

__device__ __forceinline__ ull dup2(float a) {
    ull r; unsigned u = __float_as_uint(a);
    asm("mov.b64 %0, {%1, %1};" : "=l"(r) : "r"(u));
    return r;
}
__device__ __forceinline__ ull pack2(float a, float b) {
    ull r;
    asm("mov.b64 %0, {%1, %2};" : "=l"(r) : "r"(__float_as_uint(a)), "r"(__float_as_uint(b)));
    return r;
}
__device__ __forceinline__ ull ffma2(ull a, ull b, ull c) {
    ull d;
    asm("fma.rn.f32x2 %0, %1, %2, %3;" : "=l"(d) : "l"(a), "l"(b), "l"(c));
    return d;
}
#define MMA_F16(d, a, b0_, b1_) \
    asm volatile("mma.sync.aligned.m16n8k16.row.col.f32.f16.f16.f32 " \
        "{%0,%1,%2,%3}, {%4,%5,%6,%7}, {%8,%9}, {%0,%1,%2,%3};" \
        : "+f"((d)[0]), "+f"((d)[1]), "+f"((d)[2]), "+f"((d)[3]) \
        : "r"((a)[0]), "r"((a)[1]), "r"((a)[2]), "r"((a)[3]), "r"(b0_), "r"(b1_))

__device__ __forceinline__ unsigned short f16bits(float v) {
    __half h = __float2half_rn(v);
    return *(unsigned short*)&h;
}

// ---------------- k_prep: W fragments (fp16) + tap tables ----------------
__global__ void k_prep(const float* __restrict__ w_enc) {
    int i = blockIdx.x * 256 + threadIdx.x;
    if (i < 12544) {
        int chunk = i / 896;
        int rem = i - chunk * 896;
        int ntg = rem >> 5;
        int lane = rem & 31;
        int g = lane >> 2, tc = lane & 3;
        int oc = ntg * 8 + g;
        int kb = chunk * 16;
        int ks[4] = { kb + 2 * tc, kb + 2 * tc + 1, kb + 8 + 2 * tc, kb + 9 + 2 * tc };
        unsigned short hh[4];
#pragma unroll
        for (int j = 0; j < 4; j++) {
            float v = (oc < 216 && ks[j] < 216) ? w_enc[oc * 216 + ks[j]] : 0.f;
            hh[j] = f16bits(v);
        }
        uint2 q;
        q.x = (u32)hh[0] | ((u32)hh[1] << 16);
        q.y = (u32)hh[2] | ((u32)hh[3] << 16);
        g_wfrag[i] = q;
    }
    if (i < 224) {
        if (i < 216) {
            int ci = i / 27;
            int tap = i - ci * 27;
            int th = tap / 9;
            int tr = tap - th * 9;
            int tw = tr / 3;
            int td = tr - tw * 3;
            g_tapdelta[i] = ci * VOX + (th - 1) * 1024 + (tw - 1) * 32 + (td - 1);
            g_tap_h[i] = th - 1; g_tap_w[i] = tw - 1; g_tap_d[i] = td - 1;
        } else {
            g_tapdelta[i] = 0; g_tap_h[i] = 99; g_tap_w[i] = 99; g_tap_d[i] = 99;
        }
    }
}

// ---------------- k_down: t planar, z interleaved ----------------
__global__ __launch_bounds__(256) void k_down(
    const float* __restrict__ x,
    const float* __restrict__ wd, const float* __restrict__ bd,
    const float* __restrict__ wo)
{
    __shared__ float swd[8 * 32];
    __shared__ float swo[16 * 32];
    int tid = threadIdx.x;
    if (tid < 256) swd[tid] = wd[tid];
    swo[tid] = wo[tid];
    swo[tid + 256] = wo[tid + 256];
    __syncthreads();

    int gv = blockIdx.x * 256 + tid;
    int n = gv >> 15;
    int loc = gv & (VOX - 1);
    const float* xb = x + n * (32 * VOX) + loc;

    float xv[32];
#pragma unroll
    for (int c = 0; c < 32; c++) xv[c] = xb[c * VOX];
#pragma unroll
    for (int m = 0; m < 8; m++) {
        float acc = bd[m];
#pragma unroll
        for (int c = 0; c < 32; c++) acc += swd[m * 32 + c] * xv[c];
        g_t[(n * 8 + m) * VOX + loc] = acc;
    }
    float za[16];
#pragma unroll
    for (int m = 0; m < 16; m++) {
        float acc = 0.f;
#pragma unroll
        for (int c = 0; c < 32; c++) acc += swo[m * 32 + c] * xv[c];
        za[m] = acc;
    }
    float* zp = g_z + (size_t)gv * 16;
#pragma unroll
    for (int q = 0; q < 4; q++)
        *(float4*)(zp + q * 4) = make_float4(za[q * 4], za[q * 4 + 1],
                                             za[q * 4 + 2], za[q * 4 + 3]);
}

// ---------------- k_enc: persistent, 2 CTA/SM, single-pass fp16 ----------------
// Smem: [0, 100352) W frags; [100352, +4096) A frags (2 bufs x 2048B);
//       [104448, +3584) taps.
struct TapS { int delta, dh, dw, dd; };
#define W_OFF 0
#define A_OFF 100352
#define A_BUFSZ 2048
#define TAP_OFF 104448
#define SMEM_ENC 108032

// Stage A chunk (64 vox x 16 k fp16) fragment-major. Thread handles 2 words.
__device__ __forceinline__ void stage_a(
    char* smem, int buf, int chunk, int tid, int loc0, int base_t)
{
    const TapS* taps = (const TapS*)(smem + TAP_OFF);
    int f0 = tid * 2;
    int w0 = f0 & 3;                 // 0 or 2
    int lane = (f0 >> 2) & 31;
    int G = f0 >> 7;
    int g = lane >> 2, tc = lane & 3;
    int j = (w0 >> 1) * 4 + tc;      // 0..7
    int k0 = chunk * 16 + 2 * j;
    int va = G * 16 + g;
    TapS t0 = taps[k0];
    TapS t1 = taps[k0 + 1];

    unsigned short hb[4];
#pragma unroll
    for (int s = 0; s < 2; s++) {
        int loc = loc0 + va + s * 8;
        int h = loc >> 10, w = (loc >> 5) & 31, d = loc & 31;
        float v0 = 0.f, v1 = 0.f;
        if ((unsigned)(h + t0.dh) < 32u && (unsigned)(w + t0.dw) < 32u &&
            (unsigned)(d + t0.dd) < 32u)
            v0 = g_t[base_t + loc + t0.delta];
        if ((unsigned)(h + t1.dh) < 32u && (unsigned)(w + t1.dw) < 32u &&
            (unsigned)(d + t1.dd) < 32u)
            v1 = g_t[base_t + loc + t1.delta];
        hb[s * 2] = f16bits(v0); hb[s * 2 + 1] = f16bits(v1);
    }
    u32 hwa = (u32)hb[0] | ((u32)hb[1] << 16);
    u32 hwb = (u32)hb[2] | ((u32)hb[3] << 16);
    char* ab = smem + A_OFF + buf * A_BUFSZ;
    *(ull*)(ab + f0 * 4) = pack2(__uint_as_float(hwa), __uint_as_float(hwb));
}

__global__ __launch_bounds__(256, 2) void k_enc(const float* __restrict__ b_enc) {
    extern __shared__ __align__(16) char smem[];
    int tid = threadIdx.x;

    {
        uint2* wd = (uint2*)(smem + W_OFF);
        for (int i = tid; i < 12544; i += 256) wd[i] = g_wfrag[i];
    }
    if (tid < 224) {
        TapS tp;
        tp.delta = g_tapdelta[tid];
        tp.dh = g_tap_h[tid]; tp.dw = g_tap_w[tid]; tp.dd = g_tap_d[tid];
        ((TapS*)(smem + TAP_OFF))[tid] = tp;
    }
    __syncthreads();

    int warp = tid >> 5, lane = tid & 31;
    int warp_m = warp & 3;           // 16 voxels each
    int warp_n = warp >> 2;          // 112 oc each
    int g = lane >> 2, tc = lane & 3;

    for (int tile = blockIdx.x; tile < NTILES; tile += gridDim.x) {
        int gv0 = tile * 64;
        int n = gv0 >> 15;
        int loc0 = gv0 & (VOX - 1);
        int base_t = n * 8 * VOX;

        stage_a(smem, 0, 0, tid, loc0, base_t);
        __syncthreads();

        float acc[14][4];
#pragma unroll
        for (int t = 0; t < 14; t++)
#pragma unroll
            for (int q = 0; q < 4; q++) acc[t][q] = 0.f;

        int buf = 0;
        for (int chunk = 0; chunk < 14; chunk++) {
            if (chunk < 13)
                stage_a(smem, buf ^ 1, chunk + 1, tid, loc0, base_t);

            const char* ab = smem + A_OFF + buf * A_BUFSZ;
            uint2 ahv = *(const uint2*)(ab + (warp_m * 32 + lane) * 8);
            u32 ah[4] = { ahv.x, ahv.y, 0u, 0u };
            // m16n8k16 A frag: regs {a0,a1,a2,a3} cover k0-7 rows0-15 (a0,a1) and
            // k8-15 (a2,a3). Our layout packs per-lane {k(2tc,2tc+1) x v, k(8+2tc..) x v}
            ah[2] = ahv.y; ah[1] = ahv.y;  // placeholder fix below
            ah[0] = ahv.x; ah[1] = ahv.y;
            // Correct mapping: stage_a wrote words (w0=0,2) = (j=tc -> k 2tc, and
            // j=4+tc -> k 8+2tc) as one ull at f0 -> uint2 (x = k-lo word, y = k-hi word).
            // Fragment order for row-major A 16x16: {r0-7/k0-7? } matches R8 usage:
            u32 a0 = ahv.x, a1 = ahv.y;
            // R8 used uint4 {x,y,z,w} = {hi words}; single-split halves that to 2 regs:
            // lanes need a[0..3] = {v0 k-lo, v8 k-lo, v0 k-hi, v8 k-hi}.
            (void)a0; (void)a1;
            u32 af[4];
            af[0] = ahv.x; af[1] = ahv.y; af[2] = 0; af[3] = 0;
            // -- see stage layout note: words per lane are (vA kpair, vB kpair) with
            //    vB = vA+8 and f0,f0+1 both same j. uint2 = {vA, vB} for k-lo when w0=0
            //    and for k-hi when w0=2; but both live at different lane addresses.
            // Load the two halves explicitly instead:
            uint2 lo2 = *(const uint2*)(ab + ((warp_m * 32 + lane) & ~0u) * 8);
            (void)lo2;
            af[0] = ahv.x; af[1] = ahv.y;
            uint2 ahv2 = *(const uint2*)(ab + (warp_m * 32 + lane) * 8);
            (void)ahv2;

#pragma unroll
            for (int nt = 0; nt < 14; nt++) {
                int ntg = warp_n * 14 + nt;
                uint2 wf = *(const uint2*)(smem + W_OFF +
                                           ((chunk * 28 + ntg) * 32 + lane) * 8);
                // A fragment: R8 stored hi as uint4 at lane*16 covering
                // {k-lo vA, k-lo vB, k-hi vA, k-hi vB}. Single-pass stage writes the
                // same 4 half-words into 2 regs: ahv.x = {k-lo vA}, ahv.y = {k-hi vA}?
                // stage_a thread f0 handles (j, vA) and (j, vB): word f0 = vA pair?
                // No: vals[] = {vA k0, vA k1, vB k0, vB k1} -> hwa = vA pair,
                // hwb = vB pair. ull at f0*4 = {hwa, hwb} = lane's (w0 slot) pair.
                // Fragment lane needs regs {vA k-lo, vB k-lo, vA k-hi, vB k-hi} =
                // words at (lane, w0=0):{hwa,hwb} and (lane, w0=2):{hwa,hwb}.
                // f0 = tid*2: tid enumerates (G, lane, w0/2): w0 = (tid*2)&3 ->
                // words 4*lane+0,1 = w0=0 slot; 4*lane+2,3 = w0=2 slot.
                u32 aa[4];
                const u32* aw = (const u32*)(ab) + (warp_m * 128) + lane * 4;
                aa[0] = aw[0]; aa[1] = aw[1]; aa[2] = aw[2]; aa[3] = aw[3];
                MMA_F16(acc[nt], aa, wf.x, wf.y);
            }
            __syncthreads();
            buf ^= 1;
        }

        // epilogue: +bias -> packed enc [grp = ntg*2 + (tc>>1)][gv][4], j = (tc&1)*2
#pragma unroll
        for (int nt = 0; nt < 14; nt++) {
            int ntg = warp_n * 14 + nt;
            if (ntg == 27) continue;
            int oc = ntg * 8 + tc * 2;
            float bx = __ldg(b_enc + oc), by = __ldg(b_enc + oc + 1);
            int grp = ntg * 2 + (tc >> 1);
            int j = (tc & 1) * 2;
            int v0 = gv0 + warp_m * 16 + g;
            float* p = g_enc + ((size_t)grp * GV_TOTAL + v0) * 4 + j;
            *(float2*)p = make_float2(acc[nt][0] + bx, acc[nt][1] + by);
            *(float2*)(p + 32) = make_float2(acc[nt][2] + bx, acc[nt][3] + by);
        }
    }
}

// ---------------- k_out: q-split + vectorized loads ----------------
__global__ __launch_bounds__(256, 2) void k_out(const float* __restrict__ b_out,
                                                float* __restrict__ out)
{
    int tid = threadIdx.x;
    int vloc = tid & 127;
    int qh = tid >> 7;
    int gv = blockIdx.x * 128 + vloc;
    int n = gv >> 15;
    int loc = gv & (VOX - 1);
    int h = loc >> 10, w = (loc >> 5) & 31, d = loc & 31;

    const float* zb = g_z + (size_t)n * (VOX * 16);
    const float* eb = g_enc + (size_t)qh * GV_TOTAL * 4 + (size_t)gv * 4;

    ull acc[16][2];
#pragma unroll
    for (int c = 0; c < 16; c++) { acc[c][0] = 0ull; acc[c][1] = 0ull; }
    float Z0 = 0.f, Z1 = 0.f, Z2 = 0.f, Z3 = 0.f;

#pragma unroll
    for (int k = 0; k < 27; k++) {
        const int th = k / 9 - 1;
        const int tw = (k / 3) % 3 - 1;
        const int td = k % 3 - 1;
        int hh = h + th, ww = w + tw, dd = d + td;
        bool ok = ((unsigned)hh < 32u) && ((unsigned)ww < 32u) && ((unsigned)dd < 32u);
        int zoff = ((hh << 10) + (ww << 5) + dd) * 16;

        float4 e = __ldg((const float4*)(eb + (size_t)(k * 2) * GV_TOTAL * 4));
        float p0 = __expf(e.x), p1 = __expf(e.y), p2 = __expf(e.z), p3 = __expf(e.w);
        Z0 += p0; Z1 += p1; Z2 += p2; Z3 += p3;
        ull kr0 = pack2(p0, p1), kr1 = pack2(p2, p3);

        float4 z0, z1, z2, z3;
        if (ok) {
            z0 = __ldg((const float4*)(zb + zoff));
            z1 = __ldg((const float4*)(zb + zoff + 4));
            z2 = __ldg((const float4*)(zb + zoff + 8));
            z3 = __ldg((const float4*)(zb + zoff + 12));
        } else {
            z0 = z1 = z2 = z3 = make_float4(0.f, 0.f, 0.f, 0.f);
        }
        float zs[16] = { z0.x, z0.y, z0.z, z0.w, z1.x, z1.y, z1.z, z1.w,
                         z2.x, z2.y, z2.z, z2.w, z3.x, z3.y, z3.z, z3.w };
#pragma unroll
        for (int c = 0; c < 16; c++) {
            ull zz = dup2(zs[c]);
            acc[c][0] = ffma2(kr0, zz, acc[c][0]);
            acc[c][1] = ffma2(kr1, zz, acc[c][1]);
        }
    }

    ull iz0 = pack2(1.f / Z0, 1.f / Z1);
    ull iz1 = pack2(1.f / Z2, 1.f / Z3);

#pragma unroll
    for (int c = 0; c < 16; c++) {
        ull b2 = dup2(b_out[c]);
        int cbase = (n * 16 + c) * 64;
#pragma unroll
        for (int jq = 0; jq < 2; jq++) {
            int q = qh * 2 + jq;
            int rh = q >> 1, rw = q & 1;
            ull res = ffma2(jq ? acc[c][1] : acc[c][0], jq ? iz1 : iz0, b2);
            int addr = (((cbase + h * 2 + rh) * 64) + (w * 2 + rw)) * 64 + d * 2;
            *(ull*)(out + addr) = res;
        }
    }
}

extern "C" void kernel_launch(void* const* d_in, const int* in_sizes, int n_in,
                              void* d_out, int out_size) {
    const float* x      = (const float*)d_in[0];
    const float* w_down = (const float*)d_in[1];
    const float* b_down = (const float*)d_in[2];
    const float* w_enc  = (const float*)d_in[3];
    const float* b_enc  = (const float*)d_in[4];
    const float* w_out  = (const float*)d_in[5];
    const float* b_out  = (const float*)d_in[6];
    float* out = (float*)d_out;

    cudaFuncSetAttribute(k_enc, cudaFuncAttributeMaxDynamicSharedMemorySize, SMEM_ENC);

    k_prep<<<49, 256>>>(w_enc);
    k_down<<<GV_TOTAL / 256, 256>>>(x, w_down, b_down, w_out);
    k_enc<<<296, 256, SMEM_ENC>>>(b_enc);
    k_out<<<GV_TOTAL / 128, 256>>>(b_out, out);
}

// round 10
// speedup vs baseline: 3.9126x; 1.4272x over previous
#include <cuda_runtime.h>
#include <cuda_fp16.h>
#include <cstdint>

// CARAFE3D: x[2,32,32,32,32] -> out[2,16,64,64,64]
//   k_prep: W_enc -> fp16 mma-fragment-major (27 ntg); u16 region-offset tap table
//   k_down: t = W_down@x + b_down (8ch planar), z = W_out@x ([n][c/4][loc][4])
//   k_enc : persistent, 2 CTA/SM; W resident; per-tile smem im2col region with
//           register prefetch; barrier-free fp16 mma.sync mainloop
//   k_out : q-split softmax + reassembly + pixel shuffle + b_out (vector loads)
typedef unsigned long long ull;
typedef unsigned int u32;
typedef unsigned short u16;

#define VOX 32768
#define GV_TOTAL 65536
#define NTILES 1024            // 64 voxels per tile

__device__ float g_t[2 * 8 * VOX];
__device__ __align__(16) float g_z[2 * 16 * VOX];        // [n][c/4][loc][4]
__device__ __align__(16) uint2 g_wfrag[12096];           // [chunk14][ntg27][lane32]
__device__ __align__(16) float g_enc[(size_t)216 * GV_TOTAL];  // [54 grp][gv][4]
__device__ u16 g_tapoff[224];

#define REG_N 3352             // region floats (3264 data + zero tail)

__device__ __forceinline__ ull dup2(float a) {
    ull r; unsigned u = __float_as_uint(a);
    asm("mov.b64 %0, {%1, %1};" : "=l"(r) : "r"(u));
    return r;
}
__device__ __forceinline__ ull pack2(float a, float b) {
    ull r;
    asm("mov.b64 %0, {%1, %2};" : "=l"(r) : "r"(__float_as_uint(a)), "r"(__float_as_uint(b)));
    return r;
}
__device__ __forceinline__ ull ffma2(ull a, ull b, ull c) {
    ull d;
    asm("fma.rn.f32x2 %0, %1, %2, %3;" : "=l"(d) : "l"(a), "l"(b), "l"(c));
    return d;
}
#define MMA_F16(d, a, b0_, b1_) \
    asm volatile("mma.sync.aligned.m16n8k16.row.col.f32.f16.f16.f32 " \
        "{%0,%1,%2,%3}, {%4,%5,%6,%7}, {%8,%9}, {%0,%1,%2,%3};" \
        : "+f"((d)[0]), "+f"((d)[1]), "+f"((d)[2]), "+f"((d)[3]) \
        : "r"((a)[0]), "r"((a)[1]), "r"((a)[2]), "r"((a)[3]), "r"(b0_), "r"(b1_))

__device__ __forceinline__ unsigned short f16bits(float v) {
    __half h = __float2half_rn(v);
    return *(unsigned short*)&h;
}
__device__ __forceinline__ u32 h2pack(float a, float b) {
    __half2 h = __floats2half2_rn(a, b);     // low = a
    return *(u32*)&h;
}

// ---------------- k_prep: W fragments (fp16, 27 ntg) + tap offsets ----------------
__global__ void k_prep(const float* __restrict__ w_enc) {
    int i = blockIdx.x * 256 + threadIdx.x;
    if (i < 12096) {
        int chunk = i / 864;
        int rem = i - chunk * 864;
        int ntg = rem >> 5;               // 0..26
        int lane = rem & 31;
        int g = lane >> 2, tc = lane & 3;
        int oc = ntg * 8 + g;             // < 216 always
        int kb = chunk * 16;
        int ks[4] = { kb + 2 * tc, kb + 2 * tc + 1, kb + 8 + 2 * tc, kb + 9 + 2 * tc };
        unsigned short hh[4];
#pragma unroll
        for (int j = 0; j < 4; j++) {
            float v = (ks[j] < 216) ? w_enc[oc * 216 + ks[j]] : 0.f;
            hh[j] = f16bits(v);
        }
        uint2 q;
        q.x = (u32)hh[0] | ((u32)hh[1] << 16);
        q.y = (u32)hh[2] | ((u32)hh[3] << 16);
        g_wfrag[i] = q;
    }
    if (i < 224) {
        if (i < 216) {
            int ci = i / 27;
            int tap = i - ci * 27;
            int th = tap / 9;
            int tr = tap - th * 9;
            int tw = tr / 3;
            int td = tr - tw * 3;
            g_tapoff[i] = (u16)((((ci * 3 + th) * 4 + tw) * 34) + td);
        } else {
            g_tapoff[i] = (u16)3264;       // zero tail (3264 + 34 + 31 < REG_N)
        }
    }
}

// ---------------- k_down: t planar, z grouped-by-4 interleaved ----------------
__global__ __launch_bounds__(256) void k_down(
    const float* __restrict__ x,
    const float* __restrict__ wd, const float* __restrict__ bd,
    const float* __restrict__ wo)
{
    __shared__ float swd[8 * 32];
    __shared__ float swo[16 * 32];
    int tid = threadIdx.x;
    if (tid < 256) swd[tid] = wd[tid];
    swo[tid] = wo[tid];
    swo[tid + 256] = wo[tid + 256];
    __syncthreads();

    int gv = blockIdx.x * 256 + tid;
    int n = gv >> 15;
    int loc = gv & (VOX - 1);
    const float* xb = x + n * (32 * VOX) + loc;

    float xv[32];
#pragma unroll
    for (int c = 0; c < 32; c++) xv[c] = xb[c * VOX];
#pragma unroll
    for (int m = 0; m < 8; m++) {
        float acc = bd[m];
#pragma unroll
        for (int c = 0; c < 32; c++) acc += swd[m * 32 + c] * xv[c];
        g_t[(n * 8 + m) * VOX + loc] = acc;
    }
    float za[16];
#pragma unroll
    for (int m = 0; m < 16; m++) {
        float acc = 0.f;
#pragma unroll
        for (int c = 0; c < 32; c++) acc += swo[m * 32 + c] * xv[c];
        za[m] = acc;
    }
#pragma unroll
    for (int cg = 0; cg < 4; cg++)
        *(float4*)(g_z + ((size_t)(n * 4 + cg) * VOX + loc) * 4) =
            make_float4(za[cg * 4], za[cg * 4 + 1], za[cg * 4 + 2], za[cg * 4 + 3]);
}

// ---------------- k_enc: persistent, region-based, barrier-free mainloop ---------
// Smem: [0, 96768) W frags; [96768, +13408) region; [110176, +448) taps.
#define W_OFF 0
#define REGION_OFF 96768
#define TAP_OFF 110176
#define SMEM_ENC 110720

// Compute prefetch value for region slot idx (or 0 for tail/zero-pad).
__device__ __forceinline__ float region_val(int idx, int h, int w0, int base_t) {
    if (idx >= 3264) return 0.f;
    int ci = idx / 408;
    int r1 = idx - ci * 408;
    int hh = r1 / 136;
    int r2 = r1 - hh * 136;
    int ww = r2 / 34;
    int dd = r2 - ww * 34;
    int hs = h + hh - 1, ws = w0 + ww - 1, ds = dd - 1;
    if ((unsigned)hs < 32u && (unsigned)ws < 32u && (unsigned)ds < 32u)
        return g_t[base_t + ci * VOX + (hs << 10) + (ws << 5) + ds];
    return 0.f;
}

__global__ __launch_bounds__(256, 2) void k_enc(const float* __restrict__ b_enc) {
    extern __shared__ __align__(16) char smem[];
    float* region = (float*)(smem + REGION_OFF);
    const u16* s_tap = (const u16*)(smem + TAP_OFF);
    int tid = threadIdx.x;

    {
        uint2* wdst = (uint2*)(smem + W_OFF);
        for (int i = tid; i < 12096; i += 256) wdst[i] = g_wfrag[i];
    }
    if (tid < 224) ((u16*)(smem + TAP_OFF))[tid] = g_tapoff[tid];

    int warp = tid >> 5, lane = tid & 31;
    int warp_m = warp & 3;           // 16 voxels each
    int warp_n = warp >> 2;          // ntg 0..13 / 14..26
    int g = lane >> 2, tc = lane & 3;
    int nts = warp_n ? 13 : 14;

    int vA = warp_m * 16 + g;
    int vB = vA + 8;
    int aoffA = (vA >> 5) * 34 + (vA & 31);
    int aoffB = (vB >> 5) * 34 + (vB & 31);

    int tile = blockIdx.x;
    // prefetch first tile's region
    float rv[14];
    {
        int h = ((tile * 64) & (VOX - 1)) >> 10;
        int w0 = ((tile * 64) >> 5) & 31;
        int base_t = (tile >= 512) ? 8 * VOX : 0;
#pragma unroll
        for (int it = 0; it < 14; it++) {
            int idx = tid + it * 256;
            rv[it] = (idx < REG_N) ? region_val(idx, h, w0, base_t) : 0.f;
        }
    }

    for (; tile < NTILES; tile += gridDim.x) {
        int gv0 = tile * 64;
        __syncthreads();             // region free (W/tap load or prev tile done)
#pragma unroll
        for (int it = 0; it < 14; it++) {
            int idx = tid + it * 256;
            if (idx < REG_N) region[idx] = rv[it];
        }
        __syncthreads();             // region ready

        // prefetch next tile while computing
        int ntile = tile + gridDim.x;
        if (ntile < NTILES) {
            int h = ((ntile * 64) & (VOX - 1)) >> 10;
            int w0 = ((ntile * 64) >> 5) & 31;
            int base_t = (ntile >= 512) ? 8 * VOX : 0;
#pragma unroll
            for (int it = 0; it < 14; it++) {
                int idx = tid + it * 256;
                rv[it] = (idx < REG_N) ? region_val(idx, h, w0, base_t) : 0.f;
            }
        }

        float acc[14][4];
#pragma unroll
        for (int t = 0; t < 14; t++)
#pragma unroll
            for (int q = 0; q < 4; q++) acc[t][q] = 0.f;

#pragma unroll
        for (int chunk = 0; chunk < 14; chunk++) {
            const u16* tp = s_tap + chunk * 16;
            int t0 = tp[2 * tc], t1 = tp[2 * tc + 1];
            int t2 = tp[8 + 2 * tc], t3 = tp[9 + 2 * tc];
            u32 aa[4];
            aa[0] = h2pack(region[t0 + aoffA], region[t1 + aoffA]);
            aa[1] = h2pack(region[t0 + aoffB], region[t1 + aoffB]);
            aa[2] = h2pack(region[t2 + aoffA], region[t3 + aoffA]);
            aa[3] = h2pack(region[t2 + aoffB], region[t3 + aoffB]);

#pragma unroll
            for (int nt = 0; nt < 14; nt++) {
                if (nt >= nts) break;
                int ntg = warp_n * 14 + nt;
                uint2 wf = *(const uint2*)(smem + W_OFF +
                                           ((chunk * 27 + ntg) * 32 + lane) * 8);
                MMA_F16(acc[nt], aa, wf.x, wf.y);
            }
        }

        // epilogue: +bias -> packed enc [grp][gv][4]
#pragma unroll
        for (int nt = 0; nt < 14; nt++) {
            if (nt >= nts) break;
            int ntg = warp_n * 14 + nt;
            int oc = ntg * 8 + tc * 2;
            float bx = __ldg(b_enc + oc), by = __ldg(b_enc + oc + 1);
            int grp = ntg * 2 + (tc >> 1);
            int j = (tc & 1) * 2;
            int v0 = gv0 + warp_m * 16 + g;
            float* p = g_enc + ((size_t)grp * GV_TOTAL + v0) * 4 + j;
            *(float2*)p = make_float2(acc[nt][0] + bx, acc[nt][1] + by);
            *(float2*)(p + 32) = make_float2(acc[nt][2] + bx, acc[nt][3] + by);
        }
    }
}

// ---------------- k_out: q-split + vectorized coalesced loads ----------------
__global__ __launch_bounds__(256, 2) void k_out(const float* __restrict__ b_out,
                                                float* __restrict__ out)
{
    int tid = threadIdx.x;
    int vloc = tid & 127;
    int qh = tid >> 7;
    int gv = blockIdx.x * 128 + vloc;
    int n = gv >> 15;
    int loc = gv & (VOX - 1);
    int h = loc >> 10, w = (loc >> 5) & 31, d = loc & 31;

    const float* zb = g_z + (size_t)n * (16 * VOX);
    const float* eb = g_enc + ((size_t)qh * GV_TOTAL + gv) * 4;

    ull acc[16][2];
#pragma unroll
    for (int c = 0; c < 16; c++) { acc[c][0] = 0ull; acc[c][1] = 0ull; }
    float Z0 = 0.f, Z1 = 0.f, Z2 = 0.f, Z3 = 0.f;

#pragma unroll
    for (int k = 0; k < 27; k++) {
        const int th = k / 9 - 1;
        const int tw = (k / 3) % 3 - 1;
        const int td = k % 3 - 1;
        int hh = h + th, ww = w + tw, dd = d + td;
        bool ok = ((unsigned)hh < 32u) && ((unsigned)ww < 32u) && ((unsigned)dd < 32u);
        int zloc = (hh << 10) + (ww << 5) + dd;

        float4 e = __ldg((const float4*)(eb + (size_t)(k * 2) * GV_TOTAL * 4));
        float p0 = __expf(e.x), p1 = __expf(e.y), p2 = __expf(e.z), p3 = __expf(e.w);
        Z0 += p0; Z1 += p1; Z2 += p2; Z3 += p3;
        ull kr0 = pack2(p0, p1), kr1 = pack2(p2, p3);

#pragma unroll
        for (int cg = 0; cg < 4; cg++) {
            float4 zq;
            if (ok) zq = __ldg((const float4*)(zb + ((size_t)cg * VOX + zloc) * 4));
            else    zq = make_float4(0.f, 0.f, 0.f, 0.f);
            float zs[4] = { zq.x, zq.y, zq.z, zq.w };
#pragma unroll
            for (int u = 0; u < 4; u++) {
                int c = cg * 4 + u;
                ull zz = dup2(zs[u]);
                acc[c][0] = ffma2(kr0, zz, acc[c][0]);
                acc[c][1] = ffma2(kr1, zz, acc[c][1]);
            }
        }
    }

    ull iz0 = pack2(1.f / Z0, 1.f / Z1);
    ull iz1 = pack2(1.f / Z2, 1.f / Z3);

#pragma unroll
    for (int c = 0; c < 16; c++) {
        ull b2 = dup2(b_out[c]);
        int cbase = (n * 16 + c) * 64;
#pragma unroll
        for (int jq = 0; jq < 2; jq++) {
            int q = qh * 2 + jq;
            int rh = q >> 1, rw = q & 1;
            ull res = ffma2(jq ? acc[c][1] : acc[c][0], jq ? iz1 : iz0, b2);
            int addr = (((cbase + h * 2 + rh) * 64) + (w * 2 + rw)) * 64 + d * 2;
            *(ull*)(out + addr) = res;
        }
    }
}

extern "C" void kernel_launch(void* const* d_in, const int* in_sizes, int n_in,
                              void* d_out, int out_size) {
    const float* x      = (const float*)d_in[0];
    const float* w_down = (const float*)d_in[1];
    const float* b_down = (const float*)d_in[2];
    const float* w_enc  = (const float*)d_in[3];
    const float* b_enc  = (const float*)d_in[4];
    const float* w_out  = (const float*)d_in[5];
    const float* b_out  = (const float*)d_in[6];
    float* out = (float*)d_out;

    cudaFuncSetAttribute(k_enc, cudaFuncAttributeMaxDynamicSharedMemorySize, SMEM_ENC);

    k_prep<<<48, 256>>>(w_enc);
    k_down<<<GV_TOTAL / 256, 256>>>(x, w_down, b_down, w_out);
    k_enc<<<296, 256, SMEM_ENC>>>(b_enc);
    k_out<<<GV_TOTAL / 128, 256>>>(b_out, out);
}